// round 1
// baseline (speedup 1.0000x reference)
#include <cuda_runtime.h>

#define NHEADS 16
#define HDIM   64
#define BATCH  2
#define SEQ    2048
#define DM     1024
#define MT     (BATCH*SEQ)   // 4096
#define P68    68

// Scratch (device globals: allocation-free per harness rules)
__device__ float g_q[(size_t)BATCH*NHEADS*SEQ*HDIM];
__device__ float g_k[(size_t)BATCH*NHEADS*SEQ*HDIM];
__device__ float g_v[(size_t)BATCH*NHEADS*SEQ*HDIM];
__device__ float g_attn[(size_t)MT*DM];

// ---------------------------------------------------------------------------
// NT GEMM: C[M,N] = A[M,K] @ B[N,K]^T + bias.  Tile 128x128x16, 8x8/thread.
// MODE 0: epilogue scatters into g_q/g_k/g_v ([B,H,S,Hd] layout), A = Ain (x)
// MODE 1: plain store to C, A = g_attn
// ---------------------------------------------------------------------------
template<int MODE>
__global__ __launch_bounds__(256)
void gemm_nt(const float* __restrict__ Ain, const float* __restrict__ B,
             const float* __restrict__ bias, float* __restrict__ C,
             int M, int N, int K)
{
    const float* A = (MODE == 1) ? (const float*)g_attn : Ain;
    __shared__ float As[16][132];
    __shared__ float Bs[16][132];
    const int tx = threadIdx.x, ty = threadIdx.y;
    const int tid = ty*16 + tx;
    const int m0 = blockIdx.y * 128, n0 = blockIdx.x * 128;

    float acc[8][8];
#pragma unroll
    for (int i = 0; i < 8; i++)
#pragma unroll
        for (int j = 0; j < 8; j++) acc[i][j] = 0.f;

    for (int kc = 0; kc < K; kc += 16) {
#pragma unroll
        for (int t = 0; t < 2; t++) {
            int lin = tid + t*256;
            int row = lin >> 2, c4 = lin & 3;
            float4 va = *(const float4*)(A + (size_t)(m0+row)*K + kc + c4*4);
            As[c4*4+0][row] = va.x; As[c4*4+1][row] = va.y;
            As[c4*4+2][row] = va.z; As[c4*4+3][row] = va.w;
            float4 vb = *(const float4*)(B + (size_t)(n0+row)*K + kc + c4*4);
            Bs[c4*4+0][row] = vb.x; Bs[c4*4+1][row] = vb.y;
            Bs[c4*4+2][row] = vb.z; Bs[c4*4+3][row] = vb.w;
        }
        __syncthreads();
#pragma unroll
        for (int kk = 0; kk < 16; kk++) {
            float4 a0 = *(const float4*)&As[kk][ty*8];
            float4 a1 = *(const float4*)&As[kk][ty*8+4];
            float4 b0 = *(const float4*)&Bs[kk][tx*8];
            float4 b1 = *(const float4*)&Bs[kk][tx*8+4];
            float am[8] = {a0.x,a0.y,a0.z,a0.w,a1.x,a1.y,a1.z,a1.w};
            float bn[8] = {b0.x,b0.y,b0.z,b0.w,b1.x,b1.y,b1.z,b1.w};
#pragma unroll
            for (int i = 0; i < 8; i++)
#pragma unroll
                for (int j = 0; j < 8; j++)
                    acc[i][j] += am[i]*bn[j];
        }
        __syncthreads();
    }

#pragma unroll
    for (int i = 0; i < 8; i++) {
        int m_g = m0 + ty*8 + i;
#pragma unroll
        for (int jq = 0; jq < 8; jq += 4) {
            int n_g = n0 + tx*8 + jq;
            float4 r;
            r.x = acc[i][jq+0] + bias[n_g+0];
            r.y = acc[i][jq+1] + bias[n_g+1];
            r.z = acc[i][jq+2] + bias[n_g+2];
            r.w = acc[i][jq+3] + bias[n_g+3];
            if (MODE == 0) {
                int which = n_g >> 10;          // 0=q,1=k,2=v
                int rem   = n_g & 1023;
                int hh = rem >> 6, hd = rem & 63;
                int bb = m_g >> 11, ss = m_g & 2047;
                float* buf = (which == 0) ? g_q : ((which == 1) ? g_k : g_v);
                *(float4*)(buf + ((size_t)(bb*NHEADS + hh)*SEQ + ss)*HDIM + hd) = r;
            } else {
                *(float4*)(C + (size_t)m_g*N + n_g) = r;
            }
        }
    }
}

// ---------------------------------------------------------------------------
// Flash attention: block = (b, h, 64-query tile). Key tiles of 64, causal.
// Scores & PV are 64x64x64 register-tiled GEMMs (4x4/thread, 16x16 threads).
// Online softmax via shfl.xor across the 16 lanes owning each row.
// Output written pre-transposed into g_attn as [B,S,D].
// ---------------------------------------------------------------------------
__global__ __launch_bounds__(256)
void attn_kernel()
{
    extern __shared__ float sm[];
    float* Qs = sm;                 // [64][68]  (d-major, transposed)
    float* Ks = sm + 64*P68;        // [64][68]  (d-major, transposed)
    float* Ps = sm + 2*64*P68;      // [64][68]  (k-major, transposed probs)
    float* Vs = sm + 3*64*P68;      // [64][64]  (k-major, natural)

    const int tx = threadIdx.x, ty = threadIdx.y;
    const int tid = ty*16 + tx;
    const int qt = blockIdx.x, h = blockIdx.y, b = blockIdx.z;
    const int q0 = qt*64;
    const size_t base = (size_t)(b*NHEADS + h) * SEQ * HDIM;
    const float* qb = g_q + base;
    const float* kb = g_k + base;
    const float* vb = g_v + base;

    // load Q tile transposed: Qs[d][q]
#pragma unroll
    for (int t = 0; t < 4; t++) {
        int lin = tid + t*256;
        int row = lin >> 4, c4 = lin & 15;
        float4 v = *(const float4*)(qb + (size_t)(q0+row)*HDIM + c4*4);
        Qs[(c4*4+0)*P68 + row] = v.x;
        Qs[(c4*4+1)*P68 + row] = v.y;
        Qs[(c4*4+2)*P68 + row] = v.z;
        Qs[(c4*4+3)*P68 + row] = v.w;
    }

    float acc[4][4];
    float mrow[4], lrow[4];
#pragma unroll
    for (int i = 0; i < 4; i++) {
        mrow[i] = -1e30f; lrow[i] = 0.f;
#pragma unroll
        for (int j = 0; j < 4; j++) acc[i][j] = 0.f;
    }

    for (int kt = 0; kt <= qt; kt++) {
        const int k0 = kt*64;
        __syncthreads();   // previous iteration done with Ks/Vs/Ps
#pragma unroll
        for (int t = 0; t < 4; t++) {
            int lin = tid + t*256;
            int row = lin >> 4, c4 = lin & 15;
            float4 v = *(const float4*)(kb + (size_t)(k0+row)*HDIM + c4*4);
            Ks[(c4*4+0)*P68 + row] = v.x;
            Ks[(c4*4+1)*P68 + row] = v.y;
            Ks[(c4*4+2)*P68 + row] = v.z;
            Ks[(c4*4+3)*P68 + row] = v.w;
            float4 w = *(const float4*)(vb + (size_t)(k0+row)*HDIM + c4*4);
            *(float4*)(Vs + row*64 + c4*4) = w;
        }
        __syncthreads();

        // scores S[q][k] = Q . K   (4x4 register tile)
        float s[4][4];
#pragma unroll
        for (int i = 0; i < 4; i++)
#pragma unroll
            for (int j = 0; j < 4; j++) s[i][j] = 0.f;

#pragma unroll 8
        for (int dd = 0; dd < 64; dd++) {
            float4 a  = *(const float4*)(Qs + dd*P68 + ty*4);
            float4 kv = *(const float4*)(Ks + dd*P68 + tx*4);
            float av[4]  = {a.x, a.y, a.z, a.w};
            float kvv[4] = {kv.x, kv.y, kv.z, kv.w};
#pragma unroll
            for (int i = 0; i < 4; i++)
#pragma unroll
                for (int j = 0; j < 4; j++)
                    s[i][j] += av[i]*kvv[j];
        }

        const float scale = 0.125f;   // 1/sqrt(64)
        if (kt == qt) {
#pragma unroll
            for (int i = 0; i < 4; i++) {
                int ig = ty*4 + i;
#pragma unroll
                for (int j = 0; j < 4; j++) {
                    int jg = tx*4 + j;
                    s[i][j] = (jg > ig) ? -1e30f : s[i][j]*scale;
                }
            }
        } else {
#pragma unroll
            for (int i = 0; i < 4; i++)
#pragma unroll
                for (int j = 0; j < 4; j++) s[i][j] *= scale;
        }

        // online softmax (row reduce across the 16 tx lanes)
#pragma unroll
        for (int i = 0; i < 4; i++) {
            float cm = fmaxf(fmaxf(s[i][0], s[i][1]), fmaxf(s[i][2], s[i][3]));
#pragma unroll
            for (int off = 1; off < 16; off <<= 1)
                cm = fmaxf(cm, __shfl_xor_sync(0xffffffffu, cm, off));
            float mnew  = fmaxf(mrow[i], cm);
            float alpha = __expf(mrow[i] - mnew);
            float rs = 0.f;
#pragma unroll
            for (int j = 0; j < 4; j++) {
                float p = __expf(s[i][j] - mnew);
                s[i][j] = p; rs += p;
            }
#pragma unroll
            for (int off = 1; off < 16; off <<= 1)
                rs += __shfl_xor_sync(0xffffffffu, rs, off);
            lrow[i] = lrow[i]*alpha + rs;
            mrow[i] = mnew;
#pragma unroll
            for (int j = 0; j < 4; j++) acc[i][j] *= alpha;
        }

        // write P transposed: Ps[k][q]
#pragma unroll
        for (int j = 0; j < 4; j++)
#pragma unroll
            for (int i = 0; i < 4; i++)
                Ps[(tx*4+j)*P68 + ty*4 + i] = s[i][j];
        __syncthreads();

        // O += P @ V  (4x4 register tile over 64 keys)
#pragma unroll 8
        for (int kk = 0; kk < 64; kk++) {
            float4 p  = *(const float4*)(Ps + kk*P68 + ty*4);
            float4 vv = *(const float4*)(Vs + kk*64 + tx*4);
            float pv[4]  = {p.x, p.y, p.z, p.w};
            float vvv[4] = {vv.x, vv.y, vv.z, vv.w};
#pragma unroll
            for (int i = 0; i < 4; i++)
#pragma unroll
                for (int j = 0; j < 4; j++)
                    acc[i][j] += pv[i]*vvv[j];
        }
    }

    // epilogue: normalize, write [B,S,D] so out-proj GEMM reads row-major
#pragma unroll
    for (int i = 0; i < 4; i++) {
        float inv = 1.f / lrow[i];
        int sg = q0 + ty*4 + i;
        float4 r = make_float4(acc[i][0]*inv, acc[i][1]*inv,
                               acc[i][2]*inv, acc[i][3]*inv);
        *(float4*)(g_attn + (size_t)(b*SEQ + sg)*DM + h*HDIM + tx*4) = r;
    }
}

// ---------------------------------------------------------------------------
extern "C" void kernel_launch(void* const* d_in, const int* in_sizes, int n_in,
                              void* d_out, int out_size)
{
    const float* x     = (const float*)d_in[0];
    const float* qkv_w = (const float*)d_in[1];
    const float* qkv_b = (const float*)d_in[2];
    const float* out_w = (const float*)d_in[3];
    const float* out_b = (const float*)d_in[4];
    float* out = (float*)d_out;

    const int ATTN_SMEM = (3*64*P68 + 64*64) * (int)sizeof(float);  // 68608
    cudaFuncSetAttribute(attn_kernel,
                         cudaFuncAttributeMaxDynamicSharedMemorySize, ATTN_SMEM);

    dim3 blk(16, 16);
    // QKV projection: [4096,1024] @ [3072,1024]^T -> scatter q/k/v
    gemm_nt<0><<<dim3(3*DM/128, MT/128), blk>>>(x, qkv_w, qkv_b, nullptr,
                                                MT, 3*DM, DM);
    // causal flash attention
    attn_kernel<<<dim3(SEQ/64, NHEADS, BATCH), blk, ATTN_SMEM>>>();
    // output projection: [4096,1024] @ [1024,1024]^T -> d_out
    gemm_nt<1><<<dim3(DM/128, MT/128), blk>>>(nullptr, out_w, out_b, out,
                                              MT, DM, DM);
}

// round 5
// speedup vs baseline: 1.2957x; 1.2957x over previous
#include <cuda_runtime.h>
#include <cuda_bf16.h>
#include <cstdint>

#define NHEADS 16
#define HDIM   64
#define BATCH  2
#define SEQ    2048
#define DM     1024
#define MT     (BATCH*SEQ)   // 4096
#define P68    68

// ---------------- scratch (device globals; allocation-free) ----------------
__device__ float g_q[(size_t)BATCH*NHEADS*SEQ*HDIM];
__device__ float g_k[(size_t)BATCH*NHEADS*SEQ*HDIM];
__device__ float g_v[(size_t)BATCH*NHEADS*SEQ*HDIM];
__device__ float g_attn[(size_t)MT*DM];

__device__ __nv_bfloat16 g_xh[(size_t)MT*DM],   g_xl[(size_t)MT*DM];
__device__ __nv_bfloat16 g_wh[(size_t)3*DM*DM], g_wl[(size_t)3*DM*DM];
__device__ __nv_bfloat16 g_oh[(size_t)DM*DM],   g_ol[(size_t)DM*DM];
__device__ __nv_bfloat16 g_ah[(size_t)MT*DM],   g_al[(size_t)MT*DM];

// ---------------- helpers ----------------
__device__ __forceinline__ uint32_t smem_u32(const void* p) {
    uint32_t a;
    asm("{ .reg .u64 t; cvta.to.shared.u64 t, %1; cvt.u32.u64 %0, t; }" : "=r"(a) : "l"(p));
    return a;
}
__device__ __forceinline__ void cp_async16(uint32_t dst, const void* src) {
    asm volatile("cp.async.cg.shared.global [%0], [%1], 16;" :: "r"(dst), "l"(src));
}
#define CP_COMMIT()  asm volatile("cp.async.commit_group;" ::: "memory")
#define CP_WAIT1()   asm volatile("cp.async.wait_group 1;" ::: "memory")
#define CP_WAIT0()   asm volatile("cp.async.wait_group 0;" ::: "memory")

__device__ __forceinline__ void ldsm_x4(uint32_t& r0, uint32_t& r1, uint32_t& r2, uint32_t& r3, uint32_t a) {
    asm volatile("ldmatrix.sync.aligned.m8n8.x4.shared.b16 {%0,%1,%2,%3}, [%4];"
        : "=r"(r0), "=r"(r1), "=r"(r2), "=r"(r3) : "r"(a));
}
__device__ __forceinline__ void ldsm_x2(uint32_t& r0, uint32_t& r1, uint32_t a) {
    asm volatile("ldmatrix.sync.aligned.m8n8.x2.shared.b16 {%0,%1}, [%2];"
        : "=r"(r0), "=r"(r1) : "r"(a));
}
__device__ __forceinline__ void mma_bf16(float* c, const uint32_t* a, const uint32_t* b) {
    asm volatile("mma.sync.aligned.m16n8k16.row.col.f32.bf16.bf16.f32 "
        "{%0,%1,%2,%3}, {%4,%5,%6,%7}, {%8,%9}, {%0,%1,%2,%3};"
        : "+f"(c[0]), "+f"(c[1]), "+f"(c[2]), "+f"(c[3])
        : "r"(a[0]), "r"(a[1]), "r"(a[2]), "r"(a[3]), "r"(b[0]), "r"(b[1]));
}

// ---------------------------------------------------------------------------
// split fp32 -> (hi, lo) bf16
// ---------------------------------------------------------------------------
__device__ __forceinline__ void split4(float4 v, __nv_bfloat162* hi, __nv_bfloat162* lo, size_t i2) {
    __nv_bfloat16 hx = __float2bfloat16(v.x), hy = __float2bfloat16(v.y);
    __nv_bfloat16 hz = __float2bfloat16(v.z), hw = __float2bfloat16(v.w);
    __nv_bfloat16 lx = __float2bfloat16(v.x - __bfloat162float(hx));
    __nv_bfloat16 ly = __float2bfloat16(v.y - __bfloat162float(hy));
    __nv_bfloat16 lz = __float2bfloat16(v.z - __bfloat162float(hz));
    __nv_bfloat16 lw = __float2bfloat16(v.w - __bfloat162float(hw));
    hi[i2]   = __nv_bfloat162(hx, hy);  hi[i2+1] = __nv_bfloat162(hz, hw);
    lo[i2]   = __nv_bfloat162(lx, ly);  lo[i2+1] = __nv_bfloat162(lz, lw);
}

__global__ __launch_bounds__(256)
void split_kernel(const float4* __restrict__ in, __nv_bfloat162* __restrict__ hi,
                  __nv_bfloat162* __restrict__ lo, int n4) {
    int i = blockIdx.x * blockDim.x + threadIdx.x;
    if (i < n4) split4(in[i], hi, lo, (size_t)i * 2);
}

__global__ __launch_bounds__(256)
void split_attn_kernel() {
    int i = blockIdx.x * blockDim.x + threadIdx.x;
    split4(((const float4*)g_attn)[i], (__nv_bfloat162*)g_ah, (__nv_bfloat162*)g_al, (size_t)i * 2);
}

// ---------------------------------------------------------------------------
// Warp-MMA split-bf16 NT GEMM: C[M,N] = A[M,1024] @ B[N,1024]^T + bias
// 3 accumulation segments (Ah*Bh + Al*Bh + Ah*Bl) into the same fp32 accs.
// Block 128x128, BK=32 bf16, 8 warps (4x2), warp tile 32x64 (2x8 m16n8k16).
// cp.async double-buffered SMEM, 80B-padded rows (conflict-free ldmatrix).
// MODE 0: scatter to g_q/g_k/g_v ; MODE 1: plain store to C.
// ---------------------------------------------------------------------------
#define BK      32
#define LDSM_B  80              // bytes per smem row (32 bf16 + 8 pad)
#define ASTG    (128*LDSM_B)    // 10240 B per operand per stage

template<int MODE>
__global__ __launch_bounds__(256)
void gemm_mma(const __nv_bfloat16* __restrict__ Ah, const __nv_bfloat16* __restrict__ Al,
              const __nv_bfloat16* __restrict__ Bh, const __nv_bfloat16* __restrict__ Bl,
              const float* __restrict__ bias, float* __restrict__ C, int N)
{
    constexpr int K = DM;
    constexpr int NCHUNK = 3 * (K / BK);   // 96

    extern __shared__ char smem[];
    const uint32_t sb = smem_u32(smem);
    const int tid = threadIdx.x, lane = tid & 31, warp = tid >> 5;
    const int m0 = blockIdx.y * 128, n0 = blockIdx.x * 128;
    const int wm = (warp >> 1) * 32;   // warp m offset in tile
    const int wn = (warp & 1) * 64;    // warp n offset in tile

    float acc[2][8][4];
#pragma unroll
    for (int mb = 0; mb < 2; mb++)
#pragma unroll
        for (int nb = 0; nb < 8; nb++)
#pragma unroll
            for (int r = 0; r < 4; r++) acc[mb][nb][r] = 0.f;

    // cp.async thread mapping: 2 iters x 256 threads cover 512 x 16B per operand
    const int ldr = tid >> 1;             // rows 0..127
    const int ldq = tid & 1;              // 32B half

    auto issue_stage = [&](int c, int s) {
        const int seg = c >> 5;
        const int kc = (c & 31) * BK;
        const __nv_bfloat16* Ap = (seg == 1) ? Al : Ah;
        const __nv_bfloat16* Bp = (seg == 2) ? Bl : Bh;
        const uint32_t aOff = sb + s * 2 * ASTG;
        const uint32_t bOff = aOff + ASTG;
#pragma unroll
        for (int h = 0; h < 2; h++) {
            uint32_t doff = ldr * LDSM_B + (ldq * 2 + h) * 16;
            cp_async16(aOff + doff, Ap + (size_t)(m0 + ldr) * K + kc + (ldq * 2 + h) * 8);
            cp_async16(bOff + doff, Bp + (size_t)(n0 + ldr) * K + kc + (ldq * 2 + h) * 8);
        }
    };

    issue_stage(0, 0);
    CP_COMMIT();

    for (int c = 0; c < NCHUNK; c++) {
        const int s = c & 1;
        if (c + 1 < NCHUNK) { issue_stage(c + 1, s ^ 1); CP_COMMIT(); CP_WAIT1(); }
        else                { CP_WAIT0(); }
        __syncthreads();

        const uint32_t aBase = sb + s * 2 * ASTG;
        const uint32_t bBase = aBase + ASTG;
#pragma unroll
        for (int ks = 0; ks < 2; ks++) {
            uint32_t afrag[2][4];
#pragma unroll
            for (int mb = 0; mb < 2; mb++) {
                uint32_t addr = aBase + (wm + mb * 16 + (lane & 15)) * LDSM_B
                              + (ks * 16 + (lane >> 4) * 8) * 2;
                ldsm_x4(afrag[mb][0], afrag[mb][1], afrag[mb][2], afrag[mb][3], addr);
            }
#pragma unroll
            for (int nb = 0; nb < 8; nb++) {
                uint32_t bfrag[2];
                uint32_t addr = bBase + (wn + nb * 8 + (lane & 7)) * LDSM_B
                              + (ks * 16 + ((lane >> 3) & 1) * 8) * 2;
                ldsm_x2(bfrag[0], bfrag[1], addr);
#pragma unroll
                for (int mb = 0; mb < 2; mb++)
                    mma_bf16(acc[mb][nb], afrag[mb], bfrag);
            }
        }
        __syncthreads();
    }

    // epilogue: bias + store (float2 per c-pair)
#pragma unroll
    for (int mb = 0; mb < 2; mb++) {
#pragma unroll
        for (int nb = 0; nb < 8; nb++) {
            int n_g = n0 + wn + nb * 8 + 2 * (lane & 3);
            float bx = bias[n_g], by = bias[n_g + 1];
#pragma unroll
            for (int hh = 0; hh < 2; hh++) {
                int m_g = m0 + wm + mb * 16 + (lane >> 2) + hh * 8;
                float2 v = make_float2(acc[mb][nb][hh * 2 + 0] + bx,
                                       acc[mb][nb][hh * 2 + 1] + by);
                if (MODE == 0) {
                    int which = n_g >> 10;
                    int rem = n_g & 1023;
                    int hd = rem & 63, hdh = rem >> 6;
                    int bb = m_g >> 11, ss = m_g & 2047;
                    float* buf = (which == 0) ? g_q : ((which == 1) ? g_k : g_v);
                    *(float2*)(buf + ((size_t)(bb * NHEADS + hdh) * SEQ + ss) * HDIM + hd) = v;
                } else {
                    *(float2*)(C + (size_t)m_g * N + n_g) = v;
                }
            }
        }
    }
}

// ---------------------------------------------------------------------------
// Flash attention (unchanged R1 SIMT fp32 — next round's target)
// ---------------------------------------------------------------------------
__global__ __launch_bounds__(256)
void attn_kernel()
{
    extern __shared__ float sm[];
    float* Qs = sm;
    float* Ks = sm + 64*P68;
    float* Ps = sm + 2*64*P68;
    float* Vs = sm + 3*64*P68;

    const int tx = threadIdx.x, ty = threadIdx.y;
    const int tid = ty*16 + tx;
    const int qt = blockIdx.x, h = blockIdx.y, b = blockIdx.z;
    const int q0 = qt*64;
    const size_t base = (size_t)(b*NHEADS + h) * SEQ * HDIM;
    const float* qb = g_q + base;
    const float* kb = g_k + base;
    const float* vb = g_v + base;

#pragma unroll
    for (int t = 0; t < 4; t++) {
        int lin = tid + t*256;
        int row = lin >> 4, c4 = lin & 15;
        float4 v = *(const float4*)(qb + (size_t)(q0+row)*HDIM + c4*4);
        Qs[(c4*4+0)*P68 + row] = v.x;
        Qs[(c4*4+1)*P68 + row] = v.y;
        Qs[(c4*4+2)*P68 + row] = v.z;
        Qs[(c4*4+3)*P68 + row] = v.w;
    }

    float acc[4][4];
    float mrow[4], lrow[4];
#pragma unroll
    for (int i = 0; i < 4; i++) {
        mrow[i] = -1e30f; lrow[i] = 0.f;
#pragma unroll
        for (int j = 0; j < 4; j++) acc[i][j] = 0.f;
    }

    for (int kt = 0; kt <= qt; kt++) {
        const int k0 = kt*64;
        __syncthreads();
#pragma unroll
        for (int t = 0; t < 4; t++) {
            int lin = tid + t*256;
            int row = lin >> 4, c4 = lin & 15;
            float4 v = *(const float4*)(kb + (size_t)(k0+row)*HDIM + c4*4);
            Ks[(c4*4+0)*P68 + row] = v.x;
            Ks[(c4*4+1)*P68 + row] = v.y;
            Ks[(c4*4+2)*P68 + row] = v.z;
            Ks[(c4*4+3)*P68 + row] = v.w;
            float4 w = *(const float4*)(vb + (size_t)(k0+row)*HDIM + c4*4);
            *(float4*)(Vs + row*64 + c4*4) = w;
        }
        __syncthreads();

        float s[4][4];
#pragma unroll
        for (int i = 0; i < 4; i++)
#pragma unroll
            for (int j = 0; j < 4; j++) s[i][j] = 0.f;

#pragma unroll 8
        for (int dd = 0; dd < 64; dd++) {
            float4 a  = *(const float4*)(Qs + dd*P68 + ty*4);
            float4 kv = *(const float4*)(Ks + dd*P68 + tx*4);
            float av[4]  = {a.x, a.y, a.z, a.w};
            float kvv[4] = {kv.x, kv.y, kv.z, kv.w};
#pragma unroll
            for (int i = 0; i < 4; i++)
#pragma unroll
                for (int j = 0; j < 4; j++)
                    s[i][j] += av[i]*kvv[j];
        }

        const float scale = 0.125f;
        if (kt == qt) {
#pragma unroll
            for (int i = 0; i < 4; i++) {
                int ig = ty*4 + i;
#pragma unroll
                for (int j = 0; j < 4; j++) {
                    int jg = tx*4 + j;
                    s[i][j] = (jg > ig) ? -1e30f : s[i][j]*scale;
                }
            }
        } else {
#pragma unroll
            for (int i = 0; i < 4; i++)
#pragma unroll
                for (int j = 0; j < 4; j++) s[i][j] *= scale;
        }

#pragma unroll
        for (int i = 0; i < 4; i++) {
            float cm = fmaxf(fmaxf(s[i][0], s[i][1]), fmaxf(s[i][2], s[i][3]));
#pragma unroll
            for (int off = 1; off < 16; off <<= 1)
                cm = fmaxf(cm, __shfl_xor_sync(0xffffffffu, cm, off));
            float mnew  = fmaxf(mrow[i], cm);
            float alpha = __expf(mrow[i] - mnew);
            float rs = 0.f;
#pragma unroll
            for (int j = 0; j < 4; j++) {
                float p = __expf(s[i][j] - mnew);
                s[i][j] = p; rs += p;
            }
#pragma unroll
            for (int off = 1; off < 16; off <<= 1)
                rs += __shfl_xor_sync(0xffffffffu, rs, off);
            lrow[i] = lrow[i]*alpha + rs;
            mrow[i] = mnew;
#pragma unroll
            for (int j = 0; j < 4; j++) acc[i][j] *= alpha;
        }

#pragma unroll
        for (int j = 0; j < 4; j++)
#pragma unroll
            for (int i = 0; i < 4; i++)
                Ps[(tx*4+j)*P68 + ty*4 + i] = s[i][j];
        __syncthreads();

#pragma unroll 8
        for (int kk = 0; kk < 64; kk++) {
            float4 p  = *(const float4*)(Ps + kk*P68 + ty*4);
            float4 vv = *(const float4*)(Vs + kk*64 + tx*4);
            float pv[4]  = {p.x, p.y, p.z, p.w};
            float vvv[4] = {vv.x, vv.y, vv.z, vv.w};
#pragma unroll
            for (int i = 0; i < 4; i++)
#pragma unroll
                for (int j = 0; j < 4; j++)
                    acc[i][j] += pv[i]*vvv[j];
        }
    }

#pragma unroll
    for (int i = 0; i < 4; i++) {
        float inv = 1.f / lrow[i];
        int sg = q0 + ty*4 + i;
        float4 r = make_float4(acc[i][0]*inv, acc[i][1]*inv,
                               acc[i][2]*inv, acc[i][3]*inv);
        *(float4*)(g_attn + (size_t)(b*SEQ + sg)*DM + h*HDIM + tx*4) = r;
    }
}

// ---------------------------------------------------------------------------
extern "C" void kernel_launch(void* const* d_in, const int* in_sizes, int n_in,
                              void* d_out, int out_size)
{
    const float* x     = (const float*)d_in[0];
    const float* qkv_w = (const float*)d_in[1];
    const float* qkv_b = (const float*)d_in[2];
    const float* out_w = (const float*)d_in[3];
    const float* out_b = (const float*)d_in[4];
    float* out = (float*)d_out;

    void *xh, *xl, *wh, *wl, *oh, *ol, *ah, *al;
    cudaGetSymbolAddress(&xh, g_xh); cudaGetSymbolAddress(&xl, g_xl);
    cudaGetSymbolAddress(&wh, g_wh); cudaGetSymbolAddress(&wl, g_wl);
    cudaGetSymbolAddress(&oh, g_oh); cudaGetSymbolAddress(&ol, g_ol);
    cudaGetSymbolAddress(&ah, g_ah); cudaGetSymbolAddress(&al, g_al);

    const int GEMM_SMEM = 4 * ASTG;                    // 40960
    const int ATTN_SMEM = (3*64*P68 + 64*64) * (int)sizeof(float);
    cudaFuncSetAttribute(gemm_mma<0>, cudaFuncAttributeMaxDynamicSharedMemorySize, GEMM_SMEM);
    cudaFuncSetAttribute(gemm_mma<1>, cudaFuncAttributeMaxDynamicSharedMemorySize, GEMM_SMEM);
    cudaFuncSetAttribute(attn_kernel, cudaFuncAttributeMaxDynamicSharedMemorySize, ATTN_SMEM);

    // split inputs into bf16 hi/lo
    split_kernel<<<(MT*DM/4)/256, 256>>>((const float4*)x, (__nv_bfloat162*)xh, (__nv_bfloat162*)xl, MT*DM/4);
    split_kernel<<<(3*DM*DM/4)/256, 256>>>((const float4*)qkv_w, (__nv_bfloat162*)wh, (__nv_bfloat162*)wl, 3*DM*DM/4);
    split_kernel<<<(DM*DM/4)/256, 256>>>((const float4*)out_w, (__nv_bfloat162*)oh, (__nv_bfloat162*)ol, DM*DM/4);

    // QKV projection (tensor cores) -> scatter q/k/v
    gemm_mma<0><<<dim3(3*DM/128, MT/128), 256, GEMM_SMEM>>>(
        (const __nv_bfloat16*)xh, (const __nv_bfloat16*)xl,
        (const __nv_bfloat16*)wh, (const __nv_bfloat16*)wl,
        qkv_b, nullptr, 3*DM);

    // causal flash attention (SIMT fp32)
    attn_kernel<<<dim3(SEQ/64, NHEADS, BATCH), dim3(16,16), ATTN_SMEM>>>();

    // split attention output, then out projection (tensor cores)
    split_attn_kernel<<<(MT*DM/4)/256, 256>>>();
    gemm_mma<1><<<dim3(DM/128, MT/128), 256, GEMM_SMEM>>>(
        (const __nv_bfloat16*)ah, (const __nv_bfloat16*)al,
        (const __nv_bfloat16*)oh, (const __nv_bfloat16*)ol,
        out_b, out, DM);
}

// round 7
// speedup vs baseline: 2.0410x; 1.5753x over previous
#include <cuda_runtime.h>
#include <cuda_bf16.h>
#include <cstdint>

#define NHEADS 16
#define HDIM   64
#define BATCH  2
#define SEQ    2048
#define DM     1024
#define MT     (BATCH*SEQ)   // 4096

// ---------------- scratch (device globals; allocation-free) ----------------
__device__ __nv_bfloat16 g_xh[(size_t)MT*DM],   g_xl[(size_t)MT*DM];
__device__ __nv_bfloat16 g_wh[(size_t)3*DM*DM], g_wl[(size_t)3*DM*DM];
__device__ __nv_bfloat16 g_oh[(size_t)DM*DM],   g_ol[(size_t)DM*DM];
__device__ __nv_bfloat16 g_ah[(size_t)MT*DM],   g_al[(size_t)MT*DM];
// q/k/v split bf16, [b,h,s,hd]
__device__ __nv_bfloat16 g_qh[(size_t)BATCH*NHEADS*SEQ*HDIM], g_ql[(size_t)BATCH*NHEADS*SEQ*HDIM];
__device__ __nv_bfloat16 g_kh[(size_t)BATCH*NHEADS*SEQ*HDIM], g_kl[(size_t)BATCH*NHEADS*SEQ*HDIM];
__device__ __nv_bfloat16 g_vh[(size_t)BATCH*NHEADS*SEQ*HDIM], g_vl[(size_t)BATCH*NHEADS*SEQ*HDIM];

// ---------------- helpers ----------------
__device__ __forceinline__ uint32_t smem_u32(const void* p) {
    uint32_t a;
    asm("{ .reg .u64 t; cvta.to.shared.u64 t, %1; cvt.u32.u64 %0, t; }" : "=r"(a) : "l"(p));
    return a;
}
__device__ __forceinline__ void cp_async16(uint32_t dst, const void* src) {
    asm volatile("cp.async.cg.shared.global [%0], [%1], 16;" :: "r"(dst), "l"(src));
}
#define CP_COMMIT()  asm volatile("cp.async.commit_group;" ::: "memory")
#define CP_WAIT2()   asm volatile("cp.async.wait_group 2;" ::: "memory")
#define CP_WAIT1()   asm volatile("cp.async.wait_group 1;" ::: "memory")
#define CP_WAIT0()   asm volatile("cp.async.wait_group 0;" ::: "memory")

__device__ __forceinline__ void ldsm_x4(uint32_t& r0, uint32_t& r1, uint32_t& r2, uint32_t& r3, uint32_t a) {
    asm volatile("ldmatrix.sync.aligned.m8n8.x4.shared.b16 {%0,%1,%2,%3}, [%4];"
        : "=r"(r0), "=r"(r1), "=r"(r2), "=r"(r3) : "r"(a));
}
__device__ __forceinline__ void ldsm_x2(uint32_t& r0, uint32_t& r1, uint32_t a) {
    asm volatile("ldmatrix.sync.aligned.m8n8.x2.shared.b16 {%0,%1}, [%2];"
        : "=r"(r0), "=r"(r1) : "r"(a));
}
__device__ __forceinline__ void ldsm_x2t(uint32_t& r0, uint32_t& r1, uint32_t a) {
    asm volatile("ldmatrix.sync.aligned.m8n8.x2.trans.shared.b16 {%0,%1}, [%2];"
        : "=r"(r0), "=r"(r1) : "r"(a));
}
__device__ __forceinline__ void mma_bf16(float* c, const uint32_t* a, const uint32_t* b) {
    asm volatile("mma.sync.aligned.m16n8k16.row.col.f32.bf16.bf16.f32 "
        "{%0,%1,%2,%3}, {%4,%5,%6,%7}, {%8,%9}, {%0,%1,%2,%3};"
        : "+f"(c[0]), "+f"(c[1]), "+f"(c[2]), "+f"(c[3])
        : "r"(a[0]), "r"(a[1]), "r"(a[2]), "r"(a[3]), "r"(b[0]), "r"(b[1]));
}
__device__ __forceinline__ uint32_t pack_bf16(float a, float b) {
    __nv_bfloat162 h = __nv_bfloat162(__float2bfloat16(a), __float2bfloat16(b));
    return *(uint32_t*)&h;
}

// ---------------------------------------------------------------------------
// split fp32 -> (hi, lo) bf16
// ---------------------------------------------------------------------------
__global__ __launch_bounds__(256)
void split_kernel(const float4* __restrict__ in, __nv_bfloat162* __restrict__ hi,
                  __nv_bfloat162* __restrict__ lo, int n4) {
    int i = blockIdx.x * blockDim.x + threadIdx.x;
    if (i >= n4) return;
    float4 v = in[i];
    __nv_bfloat16 hx = __float2bfloat16(v.x), hy = __float2bfloat16(v.y);
    __nv_bfloat16 hz = __float2bfloat16(v.z), hw = __float2bfloat16(v.w);
    hi[(size_t)i*2]   = __nv_bfloat162(hx, hy);
    hi[(size_t)i*2+1] = __nv_bfloat162(hz, hw);
    lo[(size_t)i*2]   = __nv_bfloat162(__float2bfloat16(v.x - __bfloat162float(hx)),
                                       __float2bfloat16(v.y - __bfloat162float(hy)));
    lo[(size_t)i*2+1] = __nv_bfloat162(__float2bfloat16(v.z - __bfloat162float(hz)),
                                       __float2bfloat16(v.w - __bfloat162float(hw)));
}

// ---------------------------------------------------------------------------
// Warp-MMA split-bf16 NT GEMM: C = A[M,1024] @ B[N,1024]^T + bias
// Block 128x128, BK=32, 8 warps (4x2), warp tile 32x64. 3-stage cp.async.
// MODE 0: split-store to q/k/v hi+lo.  MODE 1: fp32 store to C.
// ---------------------------------------------------------------------------
#define BK      32
#define LDSM_B  80
#define ASTG    (128*LDSM_B)    // 10240

template<int MODE>
__global__ __launch_bounds__(256)
void gemm_mma(const __nv_bfloat16* __restrict__ Ah, const __nv_bfloat16* __restrict__ Al,
              const __nv_bfloat16* __restrict__ Bh, const __nv_bfloat16* __restrict__ Bl,
              const float* __restrict__ bias, float* __restrict__ C, int N)
{
    constexpr int K = DM;
    constexpr int NCHUNK = 3 * (K / BK);   // 96

    extern __shared__ char smem[];
    const uint32_t sb = smem_u32(smem);
    const int tid = threadIdx.x, lane = tid & 31, warp = tid >> 5;
    const int m0 = blockIdx.y * 128, n0 = blockIdx.x * 128;
    const int wm = (warp >> 1) * 32;
    const int wn = (warp & 1) * 64;

    float acc[2][8][4];
#pragma unroll
    for (int mb = 0; mb < 2; mb++)
#pragma unroll
        for (int nb = 0; nb < 8; nb++)
#pragma unroll
            for (int r = 0; r < 4; r++) acc[mb][nb][r] = 0.f;

    const int ldr = tid >> 1;
    const int ldq = tid & 1;

    auto issue_stage = [&](int c, int s) {
        const int seg = c >> 5;
        const int kc = (c & 31) * BK;
        const __nv_bfloat16* Ap = (seg == 1) ? Al : Ah;
        const __nv_bfloat16* Bp = (seg == 2) ? Bl : Bh;
        const uint32_t aOff = sb + s * 2 * ASTG;
        const uint32_t bOff = aOff + ASTG;
#pragma unroll
        for (int h = 0; h < 2; h++) {
            uint32_t doff = ldr * LDSM_B + (ldq * 2 + h) * 16;
            cp_async16(aOff + doff, Ap + (size_t)(m0 + ldr) * K + kc + (ldq * 2 + h) * 8);
            cp_async16(bOff + doff, Bp + (size_t)(n0 + ldr) * K + kc + (ldq * 2 + h) * 8);
        }
    };

    issue_stage(0, 0); CP_COMMIT();
    issue_stage(1, 1); CP_COMMIT();

    for (int c = 0; c < NCHUNK; c++) {
        const int s = c % 3;
        if (c + 2 < NCHUNK) { issue_stage(c + 2, (c + 2) % 3); CP_COMMIT(); CP_WAIT2(); }
        else                { CP_WAIT0(); }
        __syncthreads();

        const uint32_t aBase = sb + s * 2 * ASTG;
        const uint32_t bBase = aBase + ASTG;
#pragma unroll
        for (int ks = 0; ks < 2; ks++) {
            uint32_t afrag[2][4];
#pragma unroll
            for (int mb = 0; mb < 2; mb++) {
                uint32_t addr = aBase + (wm + mb * 16 + (lane & 15)) * LDSM_B
                              + (ks * 16 + (lane >> 4) * 8) * 2;
                ldsm_x4(afrag[mb][0], afrag[mb][1], afrag[mb][2], afrag[mb][3], addr);
            }
#pragma unroll
            for (int nb = 0; nb < 8; nb++) {
                uint32_t bfrag[2];
                uint32_t addr = bBase + (wn + nb * 8 + (lane & 7)) * LDSM_B
                              + (ks * 16 + ((lane >> 3) & 1) * 8) * 2;
                ldsm_x2(bfrag[0], bfrag[1], addr);
#pragma unroll
                for (int mb = 0; mb < 2; mb++)
                    mma_bf16(acc[mb][nb], afrag[mb], bfrag);
            }
        }
        __syncthreads();
    }

#pragma unroll
    for (int mb = 0; mb < 2; mb++) {
#pragma unroll
        for (int nb = 0; nb < 8; nb++) {
            int n_g = n0 + wn + nb * 8 + 2 * (lane & 3);
            float bx = bias[n_g], by = bias[n_g + 1];
#pragma unroll
            for (int hh = 0; hh < 2; hh++) {
                int m_g = m0 + wm + mb * 16 + (lane >> 2) + hh * 8;
                float vx = acc[mb][nb][hh * 2 + 0] + bx;
                float vy = acc[mb][nb][hh * 2 + 1] + by;
                if (MODE == 0) {
                    int which = n_g >> 10;
                    int rem = n_g & 1023;
                    int hd = rem & 63, hdh = rem >> 6;
                    int bb = m_g >> 11, ss = m_g & 2047;
                    size_t off = ((size_t)(bb * NHEADS + hdh) * SEQ + ss) * HDIM + hd;
                    __nv_bfloat16 hx = __float2bfloat16(vx), hy = __float2bfloat16(vy);
                    __nv_bfloat162 hi2(hx, hy);
                    __nv_bfloat162 lo2(__float2bfloat16(vx - __bfloat162float(hx)),
                                       __float2bfloat16(vy - __bfloat162float(hy)));
                    __nv_bfloat16 *bh, *bl;
                    if (which == 0)      { bh = g_qh; bl = g_ql; }
                    else if (which == 1) { bh = g_kh; bl = g_kl; }
                    else                 { bh = g_vh; bl = g_vl; }
                    *(__nv_bfloat162*)(bh + off) = hi2;
                    *(__nv_bfloat162*)(bl + off) = lo2;
                } else {
                    *(float2*)(C + (size_t)m_g * N + n_g) = make_float2(vx, vy);
                }
            }
        }
    }
}

// ---------------------------------------------------------------------------
// MMA flash attention, split-bf16 everywhere.
// CTA: 128 q-rows (8 warps x 16), k-tiles of 64, double-buffered cp.async.
// Output written split-bf16 into g_ah/g_al as [B,S,D].
// ---------------------------------------------------------------------------
#define ALD   144                 // 64 bf16 + 8 pad, bytes per row
#define TSZ   (64*ALD)            // 9216 per tile
#define STG4  (4*TSZ)             // Kh,Kl,Vh,Vl per stage

__global__ __launch_bounds__(256)
void attn_mma()
{
    extern __shared__ char smem[];
    const uint32_t sb = smem_u32(smem);
    const int tid = threadIdx.x, lane = tid & 31, warp = tid >> 5;
    const int qt = 15 - blockIdx.x;          // heavy tiles first
    const int h = blockIdx.y, b = blockIdx.z;
    const int q0 = qt * 128;
    const size_t base = (size_t)(b * NHEADS + h) * SEQ * HDIM;
    const __nv_bfloat16 *qhp = g_qh + base, *qlp = g_ql + base;
    const __nv_bfloat16 *khp = g_kh + base, *klp = g_kl + base;
    const __nv_bfloat16 *vhp = g_vh + base, *vlp = g_vl + base;

    // ---- stage Q (hi then lo) through smem into registers ----
    uint32_t qhf[4][4], qlf[4][4];
    for (int half = 0; half < 2; half++) {
        const __nv_bfloat16* src = half ? qlp : qhp;
#pragma unroll
        for (int it = 0; it < 4; it++) {
            int ch = tid + it * 256;           // 1024 chunks = 128 rows x 8
            int row = ch >> 3, c8 = ch & 7;
            cp_async16(sb + row * ALD + c8 * 16, src + (size_t)(q0 + row) * HDIM + c8 * 8);
        }
        CP_COMMIT(); CP_WAIT0();
        __syncthreads();
        uint32_t (*qf)[4] = half ? qlf : qhf;
#pragma unroll
        for (int ks = 0; ks < 4; ks++) {
            uint32_t addr = sb + (warp * 16 + (lane & 15)) * ALD + (ks * 16 + (lane >> 4) * 8) * 2;
            ldsm_x4(qf[ks][0], qf[ks][1], qf[ks][2], qf[ks][3], addr);
        }
        __syncthreads();
    }

    float oacc[8][4];
#pragma unroll
    for (int nb = 0; nb < 8; nb++)
#pragma unroll
        for (int r = 0; r < 4; r++) oacc[nb][r] = 0.f;
    float mrow[2] = {-1e30f, -1e30f}, lrow[2] = {0.f, 0.f};

    const int nkt = 2 * (qt + 1);

    auto issue_kv = [&](int kt, int s) {
        const int k0 = kt * 64;
        const __nv_bfloat16* srcs[4] = {khp, klp, vhp, vlp};
#pragma unroll
        for (int it = 0; it < 8; it++) {
            int ch = tid + it * 256;           // 2048 chunks = 4 tiles x 64 rows x 8
            int t = ch >> 9, row = (ch >> 3) & 63, c8 = ch & 7;
            cp_async16(sb + s * STG4 + t * TSZ + row * ALD + c8 * 16,
                       srcs[t] + (size_t)(k0 + row) * HDIM + c8 * 8);
        }
    };

    issue_kv(0, 0); CP_COMMIT();

    for (int kt = 0; kt < nkt; kt++) {
        const int s = kt & 1;
        const int k0 = kt * 64;
        if (kt + 1 < nkt) { issue_kv(kt + 1, s ^ 1); CP_COMMIT(); CP_WAIT1(); }
        else              { CP_WAIT0(); }
        __syncthreads();

        const bool active = (k0 <= q0 + warp * 16 + 15);
        if (active) {
            const uint32_t khB = sb + s * STG4;
            const uint32_t klB = khB + TSZ;
            const uint32_t vhB = khB + 2 * TSZ;
            const uint32_t vlB = khB + 3 * TSZ;

            // ---- S = Q K^T  (3 split terms) ----
            float sacc[8][4];
#pragma unroll
            for (int nb = 0; nb < 8; nb++)
#pragma unroll
                for (int r = 0; r < 4; r++) sacc[nb][r] = 0.f;

#pragma unroll
            for (int ks = 0; ks < 4; ks++)
#pragma unroll
                for (int nb = 0; nb < 8; nb++) {
                    uint32_t bf[2];
                    uint32_t addr = khB + (nb * 8 + (lane & 7)) * ALD
                                  + (ks * 16 + ((lane >> 3) & 1) * 8) * 2;
                    ldsm_x2(bf[0], bf[1], addr);
                    mma_bf16(sacc[nb], qhf[ks], bf);
                    mma_bf16(sacc[nb], qlf[ks], bf);
                }
#pragma unroll
            for (int ks = 0; ks < 4; ks++)
#pragma unroll
                for (int nb = 0; nb < 8; nb++) {
                    uint32_t bf[2];
                    uint32_t addr = klB + (nb * 8 + (lane & 7)) * ALD
                                  + (ks * 16 + ((lane >> 3) & 1) * 8) * 2;
                    ldsm_x2(bf[0], bf[1], addr);
                    mma_bf16(sacc[nb], qhf[ks], bf);
                }

            // ---- scale + causal mask ----
            const float scale = 0.125f;
            const int gr0 = q0 + warp * 16 + (lane >> 2);   // rows gr0, gr0+8
            const bool need_mask = (k0 + 63 > gr0);         // conservative
#pragma unroll
            for (int nb = 0; nb < 8; nb++) {
                int col = k0 + nb * 8 + (lane & 3) * 2;
#pragma unroll
                for (int e = 0; e < 2; e++) {
                    sacc[nb][e]     = (need_mask && (col + e > gr0))     ? -1e30f : sacc[nb][e] * scale;
                    sacc[nb][e + 2] = (need_mask && (col + e > gr0 + 8)) ? -1e30f : sacc[nb][e + 2] * scale;
                }
            }

            // ---- online softmax (2 rows per thread) ----
            float alpha[2];
#pragma unroll
            for (int r = 0; r < 2; r++) {
                float m = -1e30f;
#pragma unroll
                for (int nb = 0; nb < 8; nb++)
                    m = fmaxf(m, fmaxf(sacc[nb][r * 2], sacc[nb][r * 2 + 1]));
                m = fmaxf(m, __shfl_xor_sync(0xffffffffu, m, 1));
                m = fmaxf(m, __shfl_xor_sync(0xffffffffu, m, 2));
                float mnew = fmaxf(mrow[r], m);
                alpha[r] = __expf(mrow[r] - mnew);
                float rs = 0.f;
#pragma unroll
                for (int nb = 0; nb < 8; nb++) {
                    float p0 = __expf(sacc[nb][r * 2]     - mnew);
                    float p1 = __expf(sacc[nb][r * 2 + 1] - mnew);
                    sacc[nb][r * 2] = p0; sacc[nb][r * 2 + 1] = p1;
                    rs += p0 + p1;
                }
                rs += __shfl_xor_sync(0xffffffffu, rs, 1);
                rs += __shfl_xor_sync(0xffffffffu, rs, 2);
                lrow[r] = lrow[r] * alpha[r] + rs;
                mrow[r] = mnew;
            }
#pragma unroll
            for (int nb = 0; nb < 8; nb++) {
                oacc[nb][0] *= alpha[0]; oacc[nb][1] *= alpha[0];
                oacc[nb][2] *= alpha[1]; oacc[nb][3] *= alpha[1];
            }

            // ---- P frags (hi/lo) ----
            uint32_t phf[4][4], plf[4][4];
#pragma unroll
            for (int j = 0; j < 4; j++) {
#pragma unroll
                for (int q = 0; q < 4; q++) {
                    float a = sacc[2 * j + (q >> 1)][(q & 1) * 2];
                    float bq = sacc[2 * j + (q >> 1)][(q & 1) * 2 + 1];
                    // q: 0->a0(row0,nb=2j), 1->a1(row1,nb=2j), 2->a2(row0,2j+1), 3->a3(row1,2j+1)
                    __nv_bfloat16 ha = __float2bfloat16(a), hb = __float2bfloat16(bq);
                    phf[j][q] = pack_bf16(a, bq);
                    plf[j][q] = pack_bf16(a - __bfloat162float(ha), bq - __bfloat162float(hb));
                }
            }

            // ---- O += P V  (3 split terms) ----
#pragma unroll
            for (int j = 0; j < 4; j++)
#pragma unroll
                for (int nb = 0; nb < 8; nb++) {
                    uint32_t bf[2];
                    uint32_t addr = vhB + (16 * j + (lane & 15)) * ALD + nb * 16;
                    ldsm_x2t(bf[0], bf[1], addr);
                    mma_bf16(oacc[nb], phf[j], bf);
                    mma_bf16(oacc[nb], plf[j], bf);
                }
#pragma unroll
            for (int j = 0; j < 4; j++)
#pragma unroll
                for (int nb = 0; nb < 8; nb++) {
                    uint32_t bf[2];
                    uint32_t addr = vlB + (16 * j + (lane & 15)) * ALD + nb * 16;
                    ldsm_x2t(bf[0], bf[1], addr);
                    mma_bf16(oacc[nb], phf[j], bf);
                }
        }
        __syncthreads();
    }

    // ---- epilogue: normalize, split-bf16 store to [B,S,D] ----
    float inv[2] = {1.f / lrow[0], 1.f / lrow[1]};
#pragma unroll
    for (int nb = 0; nb < 8; nb++) {
#pragma unroll
        for (int r = 0; r < 2; r++) {
            int gq = q0 + warp * 16 + (lane >> 2) + r * 8;
            float vx = oacc[nb][r * 2] * inv[r];
            float vy = oacc[nb][r * 2 + 1] * inv[r];
            size_t off = (size_t)(b * SEQ + gq) * DM + h * HDIM + nb * 8 + (lane & 3) * 2;
            __nv_bfloat16 hx = __float2bfloat16(vx), hy = __float2bfloat16(vy);
            *(__nv_bfloat162*)(g_ah + off) = __nv_bfloat162(hx, hy);
            *(__nv_bfloat162*)(g_al + off) = __nv_bfloat162(
                __float2bfloat16(vx - __bfloat162float(hx)),
                __float2bfloat16(vy - __bfloat162float(hy)));
        }
    }
}

// ---------------------------------------------------------------------------
extern "C" void kernel_launch(void* const* d_in, const int* in_sizes, int n_in,
                              void* d_out, int out_size)
{
    const float* x     = (const float*)d_in[0];
    const float* qkv_w = (const float*)d_in[1];
    const float* qkv_b = (const float*)d_in[2];
    const float* out_w = (const float*)d_in[3];
    const float* out_b = (const float*)d_in[4];
    float* out = (float*)d_out;

    void *xh, *xl, *wh, *wl, *oh, *ol, *ah, *al;
    cudaGetSymbolAddress(&xh, g_xh); cudaGetSymbolAddress(&xl, g_xl);
    cudaGetSymbolAddress(&wh, g_wh); cudaGetSymbolAddress(&wl, g_wl);
    cudaGetSymbolAddress(&oh, g_oh); cudaGetSymbolAddress(&ol, g_ol);
    cudaGetSymbolAddress(&ah, g_ah); cudaGetSymbolAddress(&al, g_al);

    const int GEMM_SMEM = 6 * ASTG;     // 61440 (3 stages)
    const int ATTN_SMEM = 2 * STG4;     // 73728 (2 stages of Kh/Kl/Vh/Vl)
    cudaFuncSetAttribute(gemm_mma<0>, cudaFuncAttributeMaxDynamicSharedMemorySize, GEMM_SMEM);
    cudaFuncSetAttribute(gemm_mma<1>, cudaFuncAttributeMaxDynamicSharedMemorySize, GEMM_SMEM);
    cudaFuncSetAttribute(attn_mma,    cudaFuncAttributeMaxDynamicSharedMemorySize, ATTN_SMEM);

    // split fp32 inputs into bf16 hi/lo
    split_kernel<<<(MT*DM/4)/256, 256>>>((const float4*)x, (__nv_bfloat162*)xh, (__nv_bfloat162*)xl, MT*DM/4);
    split_kernel<<<(3*DM*DM/4)/256, 256>>>((const float4*)qkv_w, (__nv_bfloat162*)wh, (__nv_bfloat162*)wl, 3*DM*DM/4);
    split_kernel<<<(DM*DM/4)/256, 256>>>((const float4*)out_w, (__nv_bfloat162*)oh, (__nv_bfloat162*)ol, DM*DM/4);

    // QKV projection -> split q/k/v
    gemm_mma<0><<<dim3(3*DM/128, MT/128), 256, GEMM_SMEM>>>(
        (const __nv_bfloat16*)xh, (const __nv_bfloat16*)xl,
        (const __nv_bfloat16*)wh, (const __nv_bfloat16*)wl,
        qkv_b, nullptr, 3*DM);

    // MMA flash attention -> split attn output
    attn_mma<<<dim3(SEQ/128, NHEADS, BATCH), 256, ATTN_SMEM>>>();

    // output projection -> d_out
    gemm_mma<1><<<dim3(DM/128, MT/128), 256, GEMM_SMEM>>>(
        (const __nv_bfloat16*)ah, (const __nv_bfloat16*)al,
        (const __nv_bfloat16*)oh, (const __nv_bfloat16*)ol,
        out_b, out, DM);
}

// round 8
// speedup vs baseline: 2.0901x; 1.0241x over previous
#include <cuda_runtime.h>
#include <cuda_bf16.h>
#include <cstdint>

#define NHEADS 16
#define HDIM   64
#define BATCH  2
#define SEQ    2048
#define DM     1024
#define MT     (BATCH*SEQ)   // 4096

// ---------------- scratch (device globals; allocation-free) ----------------
__device__ __nv_bfloat16 g_xh[(size_t)MT*DM],   g_xl[(size_t)MT*DM];
__device__ __nv_bfloat16 g_wh[(size_t)3*DM*DM], g_wl[(size_t)3*DM*DM];
__device__ __nv_bfloat16 g_oh[(size_t)DM*DM],   g_ol[(size_t)DM*DM];
__device__ __nv_bfloat16 g_ah[(size_t)MT*DM],   g_al[(size_t)MT*DM];
__device__ __nv_bfloat16 g_qh[(size_t)BATCH*NHEADS*SEQ*HDIM], g_ql[(size_t)BATCH*NHEADS*SEQ*HDIM];
__device__ __nv_bfloat16 g_kh[(size_t)BATCH*NHEADS*SEQ*HDIM], g_kl[(size_t)BATCH*NHEADS*SEQ*HDIM];
__device__ __nv_bfloat16 g_vh[(size_t)BATCH*NHEADS*SEQ*HDIM], g_vl[(size_t)BATCH*NHEADS*SEQ*HDIM];

// ---------------- helpers ----------------
__device__ __forceinline__ uint32_t smem_u32(const void* p) {
    uint32_t a;
    asm("{ .reg .u64 t; cvta.to.shared.u64 t, %1; cvt.u32.u64 %0, t; }" : "=r"(a) : "l"(p));
    return a;
}
__device__ __forceinline__ void cp_async16(uint32_t dst, const void* src) {
    asm volatile("cp.async.cg.shared.global [%0], [%1], 16;" :: "r"(dst), "l"(src));
}
#define CP_COMMIT()  asm volatile("cp.async.commit_group;" ::: "memory")
#define CP_WAIT1()   asm volatile("cp.async.wait_group 1;" ::: "memory")
#define CP_WAIT0()   asm volatile("cp.async.wait_group 0;" ::: "memory")

__device__ __forceinline__ void ldsm_x4(uint32_t& r0, uint32_t& r1, uint32_t& r2, uint32_t& r3, uint32_t a) {
    asm volatile("ldmatrix.sync.aligned.m8n8.x4.shared.b16 {%0,%1,%2,%3}, [%4];"
        : "=r"(r0), "=r"(r1), "=r"(r2), "=r"(r3) : "r"(a));
}
__device__ __forceinline__ void ldsm_x2(uint32_t& r0, uint32_t& r1, uint32_t a) {
    asm volatile("ldmatrix.sync.aligned.m8n8.x2.shared.b16 {%0,%1}, [%2];"
        : "=r"(r0), "=r"(r1) : "r"(a));
}
__device__ __forceinline__ void ldsm_x2t(uint32_t& r0, uint32_t& r1, uint32_t a) {
    asm volatile("ldmatrix.sync.aligned.m8n8.x2.trans.shared.b16 {%0,%1}, [%2];"
        : "=r"(r0), "=r"(r1) : "r"(a));
}
__device__ __forceinline__ void mma_bf16(float* c, const uint32_t* a, const uint32_t* b) {
    asm volatile("mma.sync.aligned.m16n8k16.row.col.f32.bf16.bf16.f32 "
        "{%0,%1,%2,%3}, {%4,%5,%6,%7}, {%8,%9}, {%0,%1,%2,%3};"
        : "+f"(c[0]), "+f"(c[1]), "+f"(c[2]), "+f"(c[3])
        : "r"(a[0]), "r"(a[1]), "r"(a[2]), "r"(a[3]), "r"(b[0]), "r"(b[1]));
}
__device__ __forceinline__ uint32_t pack_bf16(float a, float b) {
    __nv_bfloat162 h = __nv_bfloat162(__float2bfloat16(a), __float2bfloat16(b));
    return *(uint32_t*)&h;
}

// ---------------------------------------------------------------------------
// split fp32 -> (hi, lo) bf16
// ---------------------------------------------------------------------------
__global__ __launch_bounds__(256)
void split_kernel(const float4* __restrict__ in, __nv_bfloat162* __restrict__ hi,
                  __nv_bfloat162* __restrict__ lo, int n4) {
    int i = blockIdx.x * blockDim.x + threadIdx.x;
    if (i >= n4) return;
    float4 v = in[i];
    __nv_bfloat16 hx = __float2bfloat16(v.x), hy = __float2bfloat16(v.y);
    __nv_bfloat16 hz = __float2bfloat16(v.z), hw = __float2bfloat16(v.w);
    hi[(size_t)i*2]   = __nv_bfloat162(hx, hy);
    hi[(size_t)i*2+1] = __nv_bfloat162(hz, hw);
    lo[(size_t)i*2]   = __nv_bfloat162(__float2bfloat16(v.x - __bfloat162float(hx)),
                                       __float2bfloat16(v.y - __bfloat162float(hy)));
    lo[(size_t)i*2+1] = __nv_bfloat162(__float2bfloat16(v.z - __bfloat162float(hz)),
                                       __float2bfloat16(v.w - __bfloat162float(hw)));
}

// ---------------------------------------------------------------------------
// Warp-MMA split-bf16 NT GEMM. Block 128x128, BK=32, 8 warps (warp 32x64).
// 4-stage cp.async ring, prefetch distance 2, ONE __syncthreads per chunk.
// MODE 0: split-store q/k/v hi+lo.  MODE 1: fp32 store to C.
// ---------------------------------------------------------------------------
#define BK      32
#define LDSM_B  80
#define ASTG    (128*LDSM_B)    // 10240

template<int MODE>
__global__ __launch_bounds__(256, 2)
void gemm_mma(const __nv_bfloat16* __restrict__ Ah, const __nv_bfloat16* __restrict__ Al,
              const __nv_bfloat16* __restrict__ Bh, const __nv_bfloat16* __restrict__ Bl,
              const float* __restrict__ bias, float* __restrict__ C, int N)
{
    constexpr int K = DM;
    constexpr int NCHUNK = 3 * (K / BK);   // 96

    extern __shared__ char smem[];
    const uint32_t sb = smem_u32(smem);
    const int tid = threadIdx.x, lane = tid & 31, warp = tid >> 5;
    const int m0 = blockIdx.y * 128, n0 = blockIdx.x * 128;
    const int wm = (warp >> 1) * 32;
    const int wn = (warp & 1) * 64;

    float acc[2][8][4];
#pragma unroll
    for (int mb = 0; mb < 2; mb++)
#pragma unroll
        for (int nb = 0; nb < 8; nb++)
#pragma unroll
            for (int r = 0; r < 4; r++) acc[mb][nb][r] = 0.f;

    const int ldr = tid >> 1;
    const int ldq = tid & 1;

    auto issue_stage = [&](int c, int s) {
        const int seg = c >> 5;
        const int kc = (c & 31) * BK;
        const __nv_bfloat16* Ap = (seg == 1) ? Al : Ah;
        const __nv_bfloat16* Bp = (seg == 2) ? Bl : Bh;
        const uint32_t aOff = sb + s * 2 * ASTG;
        const uint32_t bOff = aOff + ASTG;
#pragma unroll
        for (int h = 0; h < 2; h++) {
            uint32_t doff = ldr * LDSM_B + (ldq * 2 + h) * 16;
            cp_async16(aOff + doff, Ap + (size_t)(m0 + ldr) * K + kc + (ldq * 2 + h) * 8);
            cp_async16(bOff + doff, Bp + (size_t)(n0 + ldr) * K + kc + (ldq * 2 + h) * 8);
        }
    };

    issue_stage(0, 0); CP_COMMIT();
    issue_stage(1, 1); CP_COMMIT();

    for (int c = 0; c < NCHUNK; c++) {
        const int s = c & 3;
        if (c + 1 < NCHUNK) CP_WAIT1(); else CP_WAIT0();
        __syncthreads();                       // single barrier per chunk
        if (c + 2 < NCHUNK) { issue_stage(c + 2, (c + 2) & 3); CP_COMMIT(); }

        const uint32_t aBase = sb + s * 2 * ASTG;
        const uint32_t bBase = aBase + ASTG;

        // hoist all A-frags for both k-steps
        uint32_t afrag[2][2][4];
#pragma unroll
        for (int ks = 0; ks < 2; ks++)
#pragma unroll
            for (int mb = 0; mb < 2; mb++) {
                uint32_t addr = aBase + (wm + mb * 16 + (lane & 15)) * LDSM_B
                              + (ks * 16 + (lane >> 4) * 8) * 2;
                ldsm_x4(afrag[ks][mb][0], afrag[ks][mb][1], afrag[ks][mb][2], afrag[ks][mb][3], addr);
            }
#pragma unroll
        for (int ks = 0; ks < 2; ks++) {
#pragma unroll
            for (int nb = 0; nb < 8; nb++) {
                uint32_t bfrag[2];
                uint32_t addr = bBase + (wn + nb * 8 + (lane & 7)) * LDSM_B
                              + (ks * 16 + ((lane >> 3) & 1) * 8) * 2;
                ldsm_x2(bfrag[0], bfrag[1], addr);
#pragma unroll
                for (int mb = 0; mb < 2; mb++)
                    mma_bf16(acc[mb][nb], afrag[ks][mb], bfrag);
            }
        }
    }

#pragma unroll
    for (int mb = 0; mb < 2; mb++) {
#pragma unroll
        for (int nb = 0; nb < 8; nb++) {
            int n_g = n0 + wn + nb * 8 + 2 * (lane & 3);
            float bx = bias[n_g], by = bias[n_g + 1];
#pragma unroll
            for (int hh = 0; hh < 2; hh++) {
                int m_g = m0 + wm + mb * 16 + (lane >> 2) + hh * 8;
                float vx = acc[mb][nb][hh * 2 + 0] + bx;
                float vy = acc[mb][nb][hh * 2 + 1] + by;
                if (MODE == 0) {
                    int which = n_g >> 10;
                    int rem = n_g & 1023;
                    int hd = rem & 63, hdh = rem >> 6;
                    int bb = m_g >> 11, ss = m_g & 2047;
                    size_t off = ((size_t)(bb * NHEADS + hdh) * SEQ + ss) * HDIM + hd;
                    __nv_bfloat16 hx = __float2bfloat16(vx), hy = __float2bfloat16(vy);
                    __nv_bfloat162 hi2(hx, hy);
                    __nv_bfloat162 lo2(__float2bfloat16(vx - __bfloat162float(hx)),
                                       __float2bfloat16(vy - __bfloat162float(hy)));
                    __nv_bfloat16 *bh, *bl;
                    if (which == 0)      { bh = g_qh; bl = g_ql; }
                    else if (which == 1) { bh = g_kh; bl = g_kl; }
                    else                 { bh = g_vh; bl = g_vl; }
                    *(__nv_bfloat162*)(bh + off) = hi2;
                    *(__nv_bfloat162*)(bl + off) = lo2;
                } else {
                    *(float2*)(C + (size_t)m_g * N + n_g) = make_float2(vx, vy);
                }
            }
        }
    }
}

// ---------------------------------------------------------------------------
// MMA flash attention, split-bf16 (unchanged from R7 except cosmetics)
// ---------------------------------------------------------------------------
#define ALD   144
#define TSZ   (64*ALD)
#define STG4  (4*TSZ)

__global__ __launch_bounds__(256)
void attn_mma()
{
    extern __shared__ char smem[];
    const uint32_t sb = smem_u32(smem);
    const int tid = threadIdx.x, lane = tid & 31, warp = tid >> 5;
    const int qt = 15 - blockIdx.x;
    const int h = blockIdx.y, b = blockIdx.z;
    const int q0 = qt * 128;
    const size_t base = (size_t)(b * NHEADS + h) * SEQ * HDIM;
    const __nv_bfloat16 *qhp = g_qh + base, *qlp = g_ql + base;
    const __nv_bfloat16 *khp = g_kh + base, *klp = g_kl + base;
    const __nv_bfloat16 *vhp = g_vh + base, *vlp = g_vl + base;

    uint32_t qhf[4][4], qlf[4][4];
    for (int half = 0; half < 2; half++) {
        const __nv_bfloat16* src = half ? qlp : qhp;
#pragma unroll
        for (int it = 0; it < 4; it++) {
            int ch = tid + it * 256;
            int row = ch >> 3, c8 = ch & 7;
            cp_async16(sb + row * ALD + c8 * 16, src + (size_t)(q0 + row) * HDIM + c8 * 8);
        }
        CP_COMMIT(); CP_WAIT0();
        __syncthreads();
        uint32_t (*qf)[4] = half ? qlf : qhf;
#pragma unroll
        for (int ks = 0; ks < 4; ks++) {
            uint32_t addr = sb + (warp * 16 + (lane & 15)) * ALD + (ks * 16 + (lane >> 4) * 8) * 2;
            ldsm_x4(qf[ks][0], qf[ks][1], qf[ks][2], qf[ks][3], addr);
        }
        __syncthreads();
    }

    float oacc[8][4];
#pragma unroll
    for (int nb = 0; nb < 8; nb++)
#pragma unroll
        for (int r = 0; r < 4; r++) oacc[nb][r] = 0.f;
    float mrow[2] = {-1e30f, -1e30f}, lrow[2] = {0.f, 0.f};

    const int nkt = 2 * (qt + 1);

    auto issue_kv = [&](int kt, int s) {
        const int k0 = kt * 64;
        const __nv_bfloat16* srcs[4] = {khp, klp, vhp, vlp};
#pragma unroll
        for (int it = 0; it < 8; it++) {
            int ch = tid + it * 256;
            int t = ch >> 9, row = (ch >> 3) & 63, c8 = ch & 7;
            cp_async16(sb + s * STG4 + t * TSZ + row * ALD + c8 * 16,
                       srcs[t] + (size_t)(k0 + row) * HDIM + c8 * 8);
        }
    };

    issue_kv(0, 0); CP_COMMIT();

    for (int kt = 0; kt < nkt; kt++) {
        const int s = kt & 1;
        const int k0 = kt * 64;
        if (kt + 1 < nkt) { issue_kv(kt + 1, s ^ 1); CP_COMMIT(); CP_WAIT1(); }
        else              { CP_WAIT0(); }
        __syncthreads();

        const bool active = (k0 <= q0 + warp * 16 + 15);
        if (active) {
            const uint32_t khB = sb + s * STG4;
            const uint32_t klB = khB + TSZ;
            const uint32_t vhB = khB + 2 * TSZ;
            const uint32_t vlB = khB + 3 * TSZ;

            float sacc[8][4];
#pragma unroll
            for (int nb = 0; nb < 8; nb++)
#pragma unroll
                for (int r = 0; r < 4; r++) sacc[nb][r] = 0.f;

#pragma unroll
            for (int ks = 0; ks < 4; ks++)
#pragma unroll
                for (int nb = 0; nb < 8; nb++) {
                    uint32_t bf[2];
                    uint32_t addr = khB + (nb * 8 + (lane & 7)) * ALD
                                  + (ks * 16 + ((lane >> 3) & 1) * 8) * 2;
                    ldsm_x2(bf[0], bf[1], addr);
                    mma_bf16(sacc[nb], qhf[ks], bf);
                    mma_bf16(sacc[nb], qlf[ks], bf);
                }
#pragma unroll
            for (int ks = 0; ks < 4; ks++)
#pragma unroll
                for (int nb = 0; nb < 8; nb++) {
                    uint32_t bf[2];
                    uint32_t addr = klB + (nb * 8 + (lane & 7)) * ALD
                                  + (ks * 16 + ((lane >> 3) & 1) * 8) * 2;
                    ldsm_x2(bf[0], bf[1], addr);
                    mma_bf16(sacc[nb], qhf[ks], bf);
                }

            const float scale = 0.125f;
            const int gr0 = q0 + warp * 16 + (lane >> 2);
            const bool need_mask = (k0 + 63 > gr0);
#pragma unroll
            for (int nb = 0; nb < 8; nb++) {
                int col = k0 + nb * 8 + (lane & 3) * 2;
#pragma unroll
                for (int e = 0; e < 2; e++) {
                    sacc[nb][e]     = (need_mask && (col + e > gr0))     ? -1e30f : sacc[nb][e] * scale;
                    sacc[nb][e + 2] = (need_mask && (col + e > gr0 + 8)) ? -1e30f : sacc[nb][e + 2] * scale;
                }
            }

            float alpha[2];
#pragma unroll
            for (int r = 0; r < 2; r++) {
                float m = -1e30f;
#pragma unroll
                for (int nb = 0; nb < 8; nb++)
                    m = fmaxf(m, fmaxf(sacc[nb][r * 2], sacc[nb][r * 2 + 1]));
                m = fmaxf(m, __shfl_xor_sync(0xffffffffu, m, 1));
                m = fmaxf(m, __shfl_xor_sync(0xffffffffu, m, 2));
                float mnew = fmaxf(mrow[r], m);
                alpha[r] = __expf(mrow[r] - mnew);
                float rs = 0.f;
#pragma unroll
                for (int nb = 0; nb < 8; nb++) {
                    float p0 = __expf(sacc[nb][r * 2]     - mnew);
                    float p1 = __expf(sacc[nb][r * 2 + 1] - mnew);
                    sacc[nb][r * 2] = p0; sacc[nb][r * 2 + 1] = p1;
                    rs += p0 + p1;
                }
                rs += __shfl_xor_sync(0xffffffffu, rs, 1);
                rs += __shfl_xor_sync(0xffffffffu, rs, 2);
                lrow[r] = lrow[r] * alpha[r] + rs;
                mrow[r] = mnew;
            }
#pragma unroll
            for (int nb = 0; nb < 8; nb++) {
                oacc[nb][0] *= alpha[0]; oacc[nb][1] *= alpha[0];
                oacc[nb][2] *= alpha[1]; oacc[nb][3] *= alpha[1];
            }

            uint32_t phf[4][4], plf[4][4];
#pragma unroll
            for (int j = 0; j < 4; j++) {
#pragma unroll
                for (int q = 0; q < 4; q++) {
                    float a = sacc[2 * j + (q >> 1)][(q & 1) * 2];
                    float bq = sacc[2 * j + (q >> 1)][(q & 1) * 2 + 1];
                    __nv_bfloat16 ha = __float2bfloat16(a), hb = __float2bfloat16(bq);
                    phf[j][q] = pack_bf16(a, bq);
                    plf[j][q] = pack_bf16(a - __bfloat162float(ha), bq - __bfloat162float(hb));
                }
            }

#pragma unroll
            for (int j = 0; j < 4; j++)
#pragma unroll
                for (int nb = 0; nb < 8; nb++) {
                    uint32_t bf[2];
                    uint32_t addr = vhB + (16 * j + (lane & 15)) * ALD + nb * 16;
                    ldsm_x2t(bf[0], bf[1], addr);
                    mma_bf16(oacc[nb], phf[j], bf);
                    mma_bf16(oacc[nb], plf[j], bf);
                }
#pragma unroll
            for (int j = 0; j < 4; j++)
#pragma unroll
                for (int nb = 0; nb < 8; nb++) {
                    uint32_t bf[2];
                    uint32_t addr = vlB + (16 * j + (lane & 15)) * ALD + nb * 16;
                    ldsm_x2t(bf[0], bf[1], addr);
                    mma_bf16(oacc[nb], phf[j], bf);
                }
        }
        __syncthreads();
    }

    float inv[2] = {1.f / lrow[0], 1.f / lrow[1]};
#pragma unroll
    for (int nb = 0; nb < 8; nb++) {
#pragma unroll
        for (int r = 0; r < 2; r++) {
            int gq = q0 + warp * 16 + (lane >> 2) + r * 8;
            float vx = oacc[nb][r * 2] * inv[r];
            float vy = oacc[nb][r * 2 + 1] * inv[r];
            size_t off = (size_t)(b * SEQ + gq) * DM + h * HDIM + nb * 8 + (lane & 3) * 2;
            __nv_bfloat16 hx = __float2bfloat16(vx), hy = __float2bfloat16(vy);
            *(__nv_bfloat162*)(g_ah + off) = __nv_bfloat162(hx, hy);
            *(__nv_bfloat162*)(g_al + off) = __nv_bfloat162(
                __float2bfloat16(vx - __bfloat162float(hx)),
                __float2bfloat16(vy - __bfloat162float(hy)));
        }
    }
}

// ---------------------------------------------------------------------------
extern "C" void kernel_launch(void* const* d_in, const int* in_sizes, int n_in,
                              void* d_out, int out_size)
{
    const float* x     = (const float*)d_in[0];
    const float* qkv_w = (const float*)d_in[1];
    const float* qkv_b = (const float*)d_in[2];
    const float* out_w = (const float*)d_in[3];
    const float* out_b = (const float*)d_in[4];
    float* out = (float*)d_out;

    void *xh, *xl, *wh, *wl, *oh, *ol, *ah, *al;
    cudaGetSymbolAddress(&xh, g_xh); cudaGetSymbolAddress(&xl, g_xl);
    cudaGetSymbolAddress(&wh, g_wh); cudaGetSymbolAddress(&wl, g_wl);
    cudaGetSymbolAddress(&oh, g_oh); cudaGetSymbolAddress(&ol, g_ol);
    cudaGetSymbolAddress(&ah, g_ah); cudaGetSymbolAddress(&al, g_al);

    const int GEMM_SMEM = 8 * ASTG;     // 81920 (4 stages x A+B)
    const int ATTN_SMEM = 2 * STG4;     // 73728
    cudaFuncSetAttribute(gemm_mma<0>, cudaFuncAttributeMaxDynamicSharedMemorySize, GEMM_SMEM);
    cudaFuncSetAttribute(gemm_mma<1>, cudaFuncAttributeMaxDynamicSharedMemorySize, GEMM_SMEM);
    cudaFuncSetAttribute(attn_mma,    cudaFuncAttributeMaxDynamicSharedMemorySize, ATTN_SMEM);

    split_kernel<<<(MT*DM/4)/256, 256>>>((const float4*)x, (__nv_bfloat162*)xh, (__nv_bfloat162*)xl, MT*DM/4);
    split_kernel<<<(3*DM*DM/4)/256, 256>>>((const float4*)qkv_w, (__nv_bfloat162*)wh, (__nv_bfloat162*)wl, 3*DM*DM/4);
    split_kernel<<<(DM*DM/4)/256, 256>>>((const float4*)out_w, (__nv_bfloat162*)oh, (__nv_bfloat162*)ol, DM*DM/4);

    gemm_mma<0><<<dim3(3*DM/128, MT/128), 256, GEMM_SMEM>>>(
        (const __nv_bfloat16*)xh, (const __nv_bfloat16*)xl,
        (const __nv_bfloat16*)wh, (const __nv_bfloat16*)wl,
        qkv_b, nullptr, 3*DM);

    attn_mma<<<dim3(SEQ/128, NHEADS, BATCH), 256, ATTN_SMEM>>>();

    gemm_mma<1><<<dim3(DM/128, MT/128), 256, GEMM_SMEM>>>(
        (const __nv_bfloat16*)ah, (const __nv_bfloat16*)al,
        (const __nv_bfloat16*)oh, (const __nv_bfloat16*)ol,
        out_b, out, DM);
}